// round 2
// baseline (speedup 1.0000x reference)
#include <cuda_runtime.h>

#define NNODES 100000
#define FIN 11
#define HH 128
#define DO 64
#define LNEPS 1e-5f

// ---------------- scratch (static device allocations are allowed) ----------------
__device__ __align__(16) float g_deg[NNODES];
__device__ __align__(16) float g_agg0[NNODES * FIN];
__device__ __align__(16) float g_h0[(size_t)NNODES * HH];
__device__ __align__(16) float g_agg1[(size_t)NNODES * HH];
__device__ __align__(16) float g_xt2[(size_t)NNODES * DO];
__device__ __align__(16) float g_agg2[(size_t)NNODES * DO];
__device__ __align__(16) float g_w0t[FIN * HH];   // k-major: w0t[k*128 + j]
__device__ __align__(16) float g_w1t[HH * HH];    // k-major: w1t[k*128 + j]
__device__ __align__(16) float g_w2t[HH * DO];    // k-major: w2t[k*64 + j]

// ---------------- init: zero deg + agg buffers ----------------
__global__ void k_init() {
    size_t i = (size_t)blockIdx.x * blockDim.x + threadIdx.x;   // float4 index
    const size_t n_deg = NNODES / 4;
    const size_t n_a0  = (size_t)NNODES * FIN / 4;
    const size_t n_a1  = (size_t)NNODES * HH / 4;
    const size_t n_a2  = (size_t)NNODES * DO / 4;
    float4 z = make_float4(0.f, 0.f, 0.f, 0.f);
    if (i < n_deg) ((float4*)g_deg)[i] = z;
    if (i < n_a0)  ((float4*)g_agg0)[i] = z;
    if (i < n_a1)  ((float4*)g_agg1)[i] = z;
    if (i < n_a2)  ((float4*)g_agg2)[i] = z;
}

// ---------------- prep: transpose weights to k-major ----------------
__global__ void k_prep(const float* __restrict__ W0, const float* __restrict__ W1,
                       const float* __restrict__ W2) {
    int i = blockIdx.x * blockDim.x + threadIdx.x;   // up to 16384
    if (i < FIN * HH) { int k = i / HH, j = i % HH; g_w0t[i] = W0[j * FIN + k]; }
    if (i < HH * HH)  { int k = i / HH, j = i % HH; g_w1t[i] = W1[j * HH + k]; }
    if (i < HH * DO)  { int k = i / DO, j = i % DO; g_w2t[i] = W2[j * HH + k]; }
}

// ---------------- layer-0 scatter: raw 11-dim features + degree ----------------
__global__ void k_scatter0(const float* __restrict__ nf, const int* __restrict__ ei, int e) {
    int t = blockIdx.x * blockDim.x + threadIdx.x;
    int eidx = t >> 4, lane = t & 15;
    if (eidx >= e) return;
    int s = ei[eidx];
    int g = ei[e + eidx];
    if (lane < FIN)
        atomicAdd(&g_agg0[(size_t)g * FIN + lane], nf[(size_t)s * FIN + lane]);
    else if (lane == FIN)
        atomicAdd(&g_deg[g], 1.0f);
}

// ---------------- fused layer 0: GEMM(11->128)/deg + b0, LN, ReLU ----------------
__global__ void __launch_bounds__(256) k_fused0(const float* __restrict__ b0,
                                                const float* __restrict__ g0,
                                                const float* __restrict__ be0, int n) {
    int gw = (blockIdx.x * blockDim.x + threadIdx.x) >> 5;
    int lane = threadIdx.x & 31;
    if (gw >= n) return;
    int node = gw;
    int j0 = lane * 4;

    float a[FIN];
#pragma unroll
    for (int k = 0; k < FIN; k++) a[k] = g_agg0[(size_t)node * FIN + k];  // broadcast

    float a0 = 0.f, a1 = 0.f, a2 = 0.f, a3 = 0.f;
#pragma unroll
    for (int k = 0; k < FIN; k++) {
        float4 w = *(const float4*)&g_w0t[k * HH + j0];
        a0 = fmaf(a[k], w.x, a0);
        a1 = fmaf(a[k], w.y, a1);
        a2 = fmaf(a[k], w.z, a2);
        a3 = fmaf(a[k], w.w, a3);
    }
    float deg = g_deg[node];
    float inv = deg > 0.f ? 1.f / deg : 0.f;
    float bm  = deg > 0.f ? 1.f : 0.f;
    float4 bv = *(const float4*)&b0[j0];
    float t0 = a0 * inv + bv.x * bm;
    float t1 = a1 * inv + bv.y * bm;
    float t2 = a2 * inv + bv.z * bm;
    float t3 = a3 * inv + bv.w * bm;

    float s = t0 + t1 + t2 + t3;
    float q = t0 * t0 + t1 * t1 + t2 * t2 + t3 * t3;
#pragma unroll
    for (int off = 16; off; off >>= 1) {
        s += __shfl_xor_sync(0xffffffffu, s, off);
        q += __shfl_xor_sync(0xffffffffu, q, off);
    }
    float mu = s * (1.f / HH);
    float var = q * (1.f / HH) - mu * mu;
    float rs = rsqrtf(var + LNEPS);
    float4 gv = *(const float4*)&g0[j0];
    float4 bev = *(const float4*)&be0[j0];
    float4 h;
    h.x = fmaxf((t0 - mu) * rs * gv.x + bev.x, 0.f);
    h.y = fmaxf((t1 - mu) * rs * gv.y + bev.y, 0.f);
    h.z = fmaxf((t2 - mu) * rs * gv.z + bev.z, 0.f);
    h.w = fmaxf((t3 - mu) * rs * gv.w + bev.w, 0.f);
    *(float4*)&g_h0[(size_t)node * HH + j0] = h;
}

// ---------------- layer-1 scatter: 128-dim, warp per edge ----------------
__global__ void k_scatter1(const int* __restrict__ ei, int e) {
    int t = blockIdx.x * blockDim.x + threadIdx.x;
    int eidx = t >> 5, lane = t & 31;
    if (eidx >= e) return;
    int s = ei[eidx];
    int g = ei[e + eidx];
    float4 v = *(const float4*)&g_h0[(size_t)s * HH + lane * 4];
    float* dst = &g_agg1[(size_t)g * HH + lane * 4];
    atomicAdd(dst + 0, v.x);
    atomicAdd(dst + 1, v.y);
    atomicAdd(dst + 2, v.z);
    atomicAdd(dst + 3, v.w);
}

// ---------------- fused layers 1+2: GEMM(128->128)/deg+b1, LN, ReLU, GEMM(128->64)+b2 ----------------
// warp owns one node-group of 4 nodes; 4 outputs/thread (layer1), 2 outputs/thread (layer2)
__global__ void __launch_bounds__(256) k_fused12(const float* __restrict__ b1,
                                                 const float* __restrict__ g1,
                                                 const float* __restrict__ be1,
                                                 const float* __restrict__ b2, int n) {
    extern __shared__ float sm[];
    float* w1s = sm;                 // 16384 floats
    float* w2s = sm + HH * HH;       // 8192 floats
    int tid = threadIdx.x, lane = tid & 31, warp = tid >> 5;
    float* h1w = sm + HH * HH + HH * DO + warp * (4 * HH);  // 4 rows per warp

    // cooperative weight staging
    {
        const float4* w1g = (const float4*)g_w1t;
        float4* d = (float4*)w1s;
        for (int i = tid; i < HH * HH / 4; i += 256) d[i] = w1g[i];
        const float4* w2g = (const float4*)g_w2t;
        float4* d2 = (float4*)w2s;
        for (int i = tid; i < HH * DO / 4; i += 256) d2[i] = w2g[i];
    }
    __syncthreads();

    int base = (blockIdx.x * 8 + warp) * 4;
    int j0 = lane * 4;

    int nd[4];
    bool val[4];
#pragma unroll
    for (int nn = 0; nn < 4; nn++) {
        int node = base + nn;
        val[nn] = node < n;
        nd[nn] = val[nn] ? node : 0;
    }

    float acc[4][4];
#pragma unroll
    for (int nn = 0; nn < 4; nn++)
#pragma unroll
        for (int i = 0; i < 4; i++) acc[nn][i] = 0.f;

    const float4* a4 = (const float4*)g_agg1;

#pragma unroll 4
    for (int kt = 0; kt < HH / 4; kt++) {
        float4 w0 = *(const float4*)&w1s[(4 * kt + 0) * HH + j0];
        float4 w1v = *(const float4*)&w1s[(4 * kt + 1) * HH + j0];
        float4 w2v = *(const float4*)&w1s[(4 * kt + 2) * HH + j0];
        float4 w3v = *(const float4*)&w1s[(4 * kt + 3) * HH + j0];
#pragma unroll
        for (int nn = 0; nn < 4; nn++) {
            float4 av = a4[(size_t)nd[nn] * (HH / 4) + kt];  // warp broadcast
            acc[nn][0] = fmaf(av.x, w0.x, fmaf(av.y, w1v.x, fmaf(av.z, w2v.x, fmaf(av.w, w3v.x, acc[nn][0]))));
            acc[nn][1] = fmaf(av.x, w0.y, fmaf(av.y, w1v.y, fmaf(av.z, w2v.y, fmaf(av.w, w3v.y, acc[nn][1]))));
            acc[nn][2] = fmaf(av.x, w0.z, fmaf(av.y, w1v.z, fmaf(av.z, w2v.z, fmaf(av.w, w3v.z, acc[nn][2]))));
            acc[nn][3] = fmaf(av.x, w0.w, fmaf(av.y, w1v.w, fmaf(av.z, w2v.w, fmaf(av.w, w3v.w, acc[nn][3]))));
        }
    }

    float4 b1v  = *(const float4*)&b1[j0];
    float4 g1v  = *(const float4*)&g1[j0];
    float4 be1v = *(const float4*)&be1[j0];

#pragma unroll
    for (int nn = 0; nn < 4; nn++) {
        if (!val[nn]) continue;            // warp-uniform branch
        float deg = g_deg[nd[nn]];
        float inv = deg > 0.f ? 1.f / deg : 0.f;
        float bm  = deg > 0.f ? 1.f : 0.f;
        float t0 = acc[nn][0] * inv + b1v.x * bm;
        float t1 = acc[nn][1] * inv + b1v.y * bm;
        float t2 = acc[nn][2] * inv + b1v.z * bm;
        float t3 = acc[nn][3] * inv + b1v.w * bm;
        float s = t0 + t1 + t2 + t3;
        float q = t0 * t0 + t1 * t1 + t2 * t2 + t3 * t3;
#pragma unroll
        for (int off = 16; off; off >>= 1) {
            s += __shfl_xor_sync(0xffffffffu, s, off);
            q += __shfl_xor_sync(0xffffffffu, q, off);
        }
        float mu = s * (1.f / HH);
        float var = q * (1.f / HH) - mu * mu;
        float rs = rsqrtf(var + LNEPS);
        float4 h;
        h.x = fmaxf((t0 - mu) * rs * g1v.x + be1v.x, 0.f);
        h.y = fmaxf((t1 - mu) * rs * g1v.y + be1v.y, 0.f);
        h.z = fmaxf((t2 - mu) * rs * g1v.z + be1v.z, 0.f);
        h.w = fmaxf((t3 - mu) * rs * g1v.w + be1v.w, 0.f);
        *(float4*)&h1w[nn * HH + j0] = h;
    }
    __syncwarp();

    // layer-2 transform: xt2 = h1 @ W2^T + b2  (bias unconditional — rides through aggregation)
    int j2 = lane * 2;
    float a2[4][2];
#pragma unroll
    for (int nn = 0; nn < 4; nn++) { a2[nn][0] = 0.f; a2[nn][1] = 0.f; }

#pragma unroll 4
    for (int kt = 0; kt < HH / 4; kt++) {
        float2 u0 = *(const float2*)&w2s[(4 * kt + 0) * DO + j2];
        float2 u1 = *(const float2*)&w2s[(4 * kt + 1) * DO + j2];
        float2 u2 = *(const float2*)&w2s[(4 * kt + 2) * DO + j2];
        float2 u3 = *(const float2*)&w2s[(4 * kt + 3) * DO + j2];
#pragma unroll
        for (int nn = 0; nn < 4; nn++) {
            float4 hv = *(const float4*)&h1w[nn * HH + 4 * kt];  // warp broadcast from smem
            a2[nn][0] = fmaf(hv.x, u0.x, fmaf(hv.y, u1.x, fmaf(hv.z, u2.x, fmaf(hv.w, u3.x, a2[nn][0]))));
            a2[nn][1] = fmaf(hv.x, u0.y, fmaf(hv.y, u1.y, fmaf(hv.z, u2.y, fmaf(hv.w, u3.y, a2[nn][1]))));
        }
    }
    float2 b2v = *(const float2*)&b2[j2];
#pragma unroll
    for (int nn = 0; nn < 4; nn++) {
        if (!val[nn]) continue;
        *(float2*)&g_xt2[(size_t)nd[nn] * DO + j2] =
            make_float2(a2[nn][0] + b2v.x, a2[nn][1] + b2v.y);
    }
}

// ---------------- layer-2 scatter: 64-dim, 16 threads per edge ----------------
__global__ void k_scatter2(const int* __restrict__ ei, int e) {
    int t = blockIdx.x * blockDim.x + threadIdx.x;
    int eidx = t >> 4, lane = t & 15;
    if (eidx >= e) return;
    int s = ei[eidx];
    int g = ei[e + eidx];
    float4 v = *(const float4*)&g_xt2[(size_t)s * DO + lane * 4];
    float* dst = &g_agg2[(size_t)g * DO + lane * 4];
    atomicAdd(dst + 0, v.x);
    atomicAdd(dst + 1, v.y);
    atomicAdd(dst + 2, v.z);
    atomicAdd(dst + 3, v.w);
}

// ---------------- final: /deg + LN over 64 dims, warp per node ----------------
__global__ void __launch_bounds__(256) k_final(const float* __restrict__ g2,
                                               const float* __restrict__ be2,
                                               float* __restrict__ out, int n) {
    int gw = (blockIdx.x * blockDim.x + threadIdx.x) >> 5;
    int lane = threadIdx.x & 31;
    if (gw >= n) return;
    float deg = g_deg[gw];
    float inv = deg > 0.f ? 1.f / deg : 0.f;   // agg2 row is 0 when deg==0 -> LN(0)=be2, matches ref
    float v0 = g_agg2[(size_t)gw * DO + lane] * inv;
    float v1 = g_agg2[(size_t)gw * DO + 32 + lane] * inv;
    float s = v0 + v1, q = v0 * v0 + v1 * v1;
#pragma unroll
    for (int off = 16; off; off >>= 1) {
        s += __shfl_xor_sync(0xffffffffu, s, off);
        q += __shfl_xor_sync(0xffffffffu, q, off);
    }
    float mu = s * (1.f / DO);
    float var = q * (1.f / DO) - mu * mu;
    float rs = rsqrtf(var + LNEPS);
    out[(size_t)gw * DO + lane]      = (v0 - mu) * rs * g2[lane] + be2[lane];
    out[(size_t)gw * DO + 32 + lane] = (v1 - mu) * rs * g2[lane + 32] + be2[lane + 32];
}

// ---------------- launch ----------------
extern "C" void kernel_launch(void* const* d_in, const int* in_sizes, int n_in,
                              void* d_out, int out_size) {
    const float* nf  = (const float*)d_in[0];
    const int*   ei  = (const int*)d_in[1];
    const float* W0  = (const float*)d_in[2];
    const float* b0  = (const float*)d_in[3];
    const float* W1  = (const float*)d_in[4];
    const float* b1  = (const float*)d_in[5];
    const float* W2  = (const float*)d_in[6];
    const float* b2  = (const float*)d_in[7];
    const float* g0  = (const float*)d_in[8];
    const float* be0 = (const float*)d_in[9];
    const float* g1  = (const float*)d_in[10];
    const float* be1 = (const float*)d_in[11];
    const float* g2  = (const float*)d_in[12];
    const float* be2 = (const float*)d_in[13];
    float* out = (float*)d_out;

    int n = in_sizes[0] / FIN;
    int e = in_sizes[1] / 2;

    // zero scratch (largest segment: n*128/4 float4)
    {
        int total4 = (NNODES * HH) / 4;
        k_init<<<(total4 + 255) / 256, 256>>>();
    }
    k_prep<<<(HH * HH + 255) / 256, 256>>>(W0, W1, W2);
    k_scatter0<<<(e * 16 + 255) / 256, 256>>>(nf, ei, e);
    k_fused0<<<(n + 7) / 8, 256>>>(b0, g0, be0, n);
    k_scatter1<<<(e * 32 + 255) / 256, 256>>>(ei, e);

    const int smem12 = (HH * HH + HH * DO + 8 * 4 * HH) * (int)sizeof(float);  // 114688 B
    cudaFuncSetAttribute(k_fused12, cudaFuncAttributeMaxDynamicSharedMemorySize, smem12);
    k_fused12<<<(n + 31) / 32, 256, smem12>>>(b1, g1, be1, b2, n);

    k_scatter2<<<(e * 16 + 255) / 256, 256>>>(ei, e);
    k_final<<<(n + 7) / 8, 256>>>(g2, be2, out, n);
}

// round 3
// speedup vs baseline: 2.4764x; 2.4764x over previous
#include <cuda_runtime.h>

#define NNODES 100000
#define NEDGES 1600000
#define FIN 11
#define HH 128
#define DO 64
#define LNEPS 1e-5f
#define NB ((NNODES + 1023) / 1024)   // 98 scan blocks

// ---------------- scratch ----------------
__device__ int g_cnt[NNODES];          // histogram, then fill cursor
__device__ int g_rowptr[NNODES + 1];
__device__ int g_bsum[128];
__device__ int g_csr[NEDGES];
__device__ __align__(16) float g_h0[(size_t)NNODES * HH];
__device__ __align__(16) float g_xt2[(size_t)NNODES * DO];
__device__ __align__(16) float g_w0t[FIN * HH];   // k-major
__device__ __align__(16) float g_w1t[HH * HH];    // k-major
__device__ __align__(16) float g_w2t[HH * DO];    // k-major

// ---------------- init: zero histogram ----------------
__global__ void k_init() {
    int i = blockIdx.x * blockDim.x + threadIdx.x;
    if (i < NNODES) g_cnt[i] = 0;
}

// ---------------- prep: transpose weights to k-major ----------------
__global__ void k_prep(const float* __restrict__ W0, const float* __restrict__ W1,
                       const float* __restrict__ W2) {
    int i = blockIdx.x * blockDim.x + threadIdx.x;
    if (i < FIN * HH) { int k = i / HH, j = i % HH; g_w0t[i] = W0[j * FIN + k]; }
    if (i < HH * HH)  { int k = i / HH, j = i % HH; g_w1t[i] = W1[j * HH + k]; }
    if (i < HH * DO)  { int k = i / DO, j = i % DO; g_w2t[i] = W2[j * HH + k]; }
}

// ---------------- CSR build ----------------
__global__ void k_hist(const int* __restrict__ ei, int e) {
    int t = blockIdx.x * blockDim.x + threadIdx.x;
    if (t < e) atomicAdd(&g_cnt[ei[e + t]], 1);
}

__global__ void __launch_bounds__(1024) k_scanA(int n) {
    __shared__ int sm[1024];
    int tid = threadIdx.x;
    int i = blockIdx.x * 1024 + tid;
    int v = (i < n) ? g_cnt[i] : 0;
    sm[tid] = v;
    __syncthreads();
#pragma unroll
    for (int off = 1; off < 1024; off <<= 1) {
        int t = (tid >= off) ? sm[tid - off] : 0;
        __syncthreads();
        sm[tid] += t;
        __syncthreads();
    }
    if (i < n) g_rowptr[i] = sm[tid] - v;            // block-local exclusive
    if (tid == 1023) g_bsum[blockIdx.x] = sm[1023];  // block total
}

__global__ void k_scanB() {
    __shared__ int sm[128];
    int tid = threadIdx.x;
    int v = (tid < NB) ? g_bsum[tid] : 0;
    sm[tid] = v;
    __syncthreads();
#pragma unroll
    for (int off = 1; off < 128; off <<= 1) {
        int t = (tid >= off) ? sm[tid - off] : 0;
        __syncthreads();
        sm[tid] += t;
        __syncthreads();
    }
    if (tid < NB) g_bsum[tid] = sm[tid] - v;         // exclusive block offsets
}

__global__ void k_scanC(int n, int e) {
    int i = blockIdx.x * blockDim.x + threadIdx.x;
    if (i < n) {
        g_rowptr[i] += g_bsum[i >> 10];
        g_cnt[i] = 0;                                 // reset -> fill cursor
    }
    if (i == 0) g_rowptr[n] = e;
}

__global__ void k_fill(const int* __restrict__ ei, int e) {
    int t = blockIdx.x * blockDim.x + threadIdx.x;
    if (t >= e) return;
    int tg = ei[e + t];
    int pos = atomicAdd(&g_cnt[tg], 1);
    g_csr[g_rowptr[tg] + pos] = ei[t];
}

// ---------------- fused layer 0: gather(11-dim) + GEMM(11->128)/deg + b0, LN, ReLU ----------------
__global__ void __launch_bounds__(256) k_fused0g(const float* __restrict__ nf,
                                                 const float* __restrict__ b0,
                                                 const float* __restrict__ g0,
                                                 const float* __restrict__ be0, int n) {
    int gw = (blockIdx.x * blockDim.x + threadIdx.x) >> 5;
    int lane = threadIdx.x & 31;
    if (gw >= n) return;
    int rp0 = g_rowptr[gw], rp1 = g_rowptr[gw + 1];

    // gather raw features: lanes 0..10 accumulate one dim each
    float accv = 0.f;
    int j = rp0;
    for (; j + 3 < rp1; j += 4) {
        int s0 = g_csr[j], s1 = g_csr[j + 1], s2 = g_csr[j + 2], s3 = g_csr[j + 3];
        if (lane < FIN) {
            float v0 = nf[(size_t)s0 * FIN + lane];
            float v1 = nf[(size_t)s1 * FIN + lane];
            float v2 = nf[(size_t)s2 * FIN + lane];
            float v3 = nf[(size_t)s3 * FIN + lane];
            accv += v0; accv += v1; accv += v2; accv += v3;
        }
    }
    for (; j < rp1; j++) {
        int s = g_csr[j];
        if (lane < FIN) accv += nf[(size_t)s * FIN + lane];
    }

    float a[FIN];
#pragma unroll
    for (int k = 0; k < FIN; k++) a[k] = __shfl_sync(0xffffffffu, accv, k);

    int d = rp1 - rp0;
    float inv = d > 0 ? 1.f / (float)d : 0.f;
    float bm  = d > 0 ? 1.f : 0.f;

    int j0 = lane * 4;
    float a0 = 0.f, a1 = 0.f, a2 = 0.f, a3 = 0.f;
#pragma unroll
    for (int k = 0; k < FIN; k++) {
        float4 w = *(const float4*)&g_w0t[k * HH + j0];
        a0 = fmaf(a[k], w.x, a0);
        a1 = fmaf(a[k], w.y, a1);
        a2 = fmaf(a[k], w.z, a2);
        a3 = fmaf(a[k], w.w, a3);
    }
    float4 bv = *(const float4*)&b0[j0];
    float t0 = a0 * inv + bv.x * bm;
    float t1 = a1 * inv + bv.y * bm;
    float t2 = a2 * inv + bv.z * bm;
    float t3 = a3 * inv + bv.w * bm;

    float s = t0 + t1 + t2 + t3;
    float q = t0 * t0 + t1 * t1 + t2 * t2 + t3 * t3;
#pragma unroll
    for (int off = 16; off; off >>= 1) {
        s += __shfl_xor_sync(0xffffffffu, s, off);
        q += __shfl_xor_sync(0xffffffffu, q, off);
    }
    float mu = s * (1.f / HH);
    float var = q * (1.f / HH) - mu * mu;
    float rs = rsqrtf(var + LNEPS);
    float4 gv = *(const float4*)&g0[j0];
    float4 bev = *(const float4*)&be0[j0];
    float4 h;
    h.x = fmaxf((t0 - mu) * rs * gv.x + bev.x, 0.f);
    h.y = fmaxf((t1 - mu) * rs * gv.y + bev.y, 0.f);
    h.z = fmaxf((t2 - mu) * rs * gv.z + bev.z, 0.f);
    h.w = fmaxf((t3 - mu) * rs * gv.w + bev.w, 0.f);
    *(float4*)&g_h0[(size_t)gw * HH + j0] = h;
}

// ---------------- fused layers 1+2: gather(h0) + GEMM/deg+b1 + LN + ReLU + GEMM2 + b2 ----------------
__global__ void __launch_bounds__(256) k_fused12g(const float* __restrict__ b1,
                                                  const float* __restrict__ g1,
                                                  const float* __restrict__ be1,
                                                  const float* __restrict__ b2, int n) {
    extern __shared__ float sm[];
    float* w1s = sm;                 // 16384 floats
    float* w2s = sm + HH * HH;       // 8192 floats
    int tid = threadIdx.x, lane = tid & 31, warp = tid >> 5;
    float* aw = sm + HH * HH + HH * DO + warp * (4 * HH);  // per-warp staging, 4 rows

    // cooperative weight staging
    {
        const float4* w1g = (const float4*)g_w1t;
        float4* d = (float4*)w1s;
        for (int i = tid; i < HH * HH / 4; i += 256) d[i] = w1g[i];
        const float4* w2g = (const float4*)g_w2t;
        float4* d2 = (float4*)w2s;
        for (int i = tid; i < HH * DO / 4; i += 256) d2[i] = w2g[i];
    }
    __syncthreads();

    int base = (blockIdx.x * 8 + warp) * 4;
    int j0 = lane * 4;

    int nd[4];
    bool val[4];
    int degs[4];
#pragma unroll
    for (int nn = 0; nn < 4; nn++) {
        int node = base + nn;
        val[nn] = node < n;
        nd[nn] = val[nn] ? node : 0;
    }

    // ---- gather h0 rows into staging (replaces atomic scatter + agg1 buffer) ----
#pragma unroll
    for (int nn = 0; nn < 4; nn++) {
        if (!val[nn]) { degs[nn] = 0; continue; }     // warp-uniform
        int rp0 = g_rowptr[nd[nn]], rp1 = g_rowptr[nd[nn] + 1];
        degs[nn] = rp1 - rp0;
        float4 acc = make_float4(0.f, 0.f, 0.f, 0.f);
        int j = rp0;
        for (; j + 3 < rp1; j += 4) {
            int s0 = g_csr[j], s1 = g_csr[j + 1], s2 = g_csr[j + 2], s3 = g_csr[j + 3];
            float4 v0 = *(const float4*)&g_h0[(size_t)s0 * HH + j0];
            float4 v1 = *(const float4*)&g_h0[(size_t)s1 * HH + j0];
            float4 v2 = *(const float4*)&g_h0[(size_t)s2 * HH + j0];
            float4 v3 = *(const float4*)&g_h0[(size_t)s3 * HH + j0];
            acc.x += v0.x; acc.y += v0.y; acc.z += v0.z; acc.w += v0.w;
            acc.x += v1.x; acc.y += v1.y; acc.z += v1.z; acc.w += v1.w;
            acc.x += v2.x; acc.y += v2.y; acc.z += v2.z; acc.w += v2.w;
            acc.x += v3.x; acc.y += v3.y; acc.z += v3.z; acc.w += v3.w;
        }
        for (; j < rp1; j++) {
            int s = g_csr[j];
            float4 v = *(const float4*)&g_h0[(size_t)s * HH + j0];
            acc.x += v.x; acc.y += v.y; acc.z += v.z; acc.w += v.w;
        }
        *(float4*)&aw[nn * HH + j0] = acc;
    }
    __syncwarp();

    // ---- GEMM1 from staging (warp-broadcast LDS) ----
    float acc[4][4];
#pragma unroll
    for (int nn = 0; nn < 4; nn++)
#pragma unroll
        for (int i = 0; i < 4; i++) acc[nn][i] = 0.f;

#pragma unroll 4
    for (int kt = 0; kt < HH / 4; kt++) {
        float4 w0 = *(const float4*)&w1s[(4 * kt + 0) * HH + j0];
        float4 w1v = *(const float4*)&w1s[(4 * kt + 1) * HH + j0];
        float4 w2v = *(const float4*)&w1s[(4 * kt + 2) * HH + j0];
        float4 w3v = *(const float4*)&w1s[(4 * kt + 3) * HH + j0];
#pragma unroll
        for (int nn = 0; nn < 4; nn++) {
            float4 av = *(const float4*)&aw[nn * HH + 4 * kt];   // broadcast
            acc[nn][0] = fmaf(av.x, w0.x, fmaf(av.y, w1v.x, fmaf(av.z, w2v.x, fmaf(av.w, w3v.x, acc[nn][0]))));
            acc[nn][1] = fmaf(av.x, w0.y, fmaf(av.y, w1v.y, fmaf(av.z, w2v.y, fmaf(av.w, w3v.y, acc[nn][1]))));
            acc[nn][2] = fmaf(av.x, w0.z, fmaf(av.y, w1v.z, fmaf(av.z, w2v.z, fmaf(av.w, w3v.z, acc[nn][2]))));
            acc[nn][3] = fmaf(av.x, w0.w, fmaf(av.y, w1v.w, fmaf(av.z, w2v.w, fmaf(av.w, w3v.w, acc[nn][3]))));
        }
    }
    __syncwarp();   // GEMM1 reads of aw complete before LN overwrites it

    float4 b1v  = *(const float4*)&b1[j0];
    float4 g1v  = *(const float4*)&g1[j0];
    float4 be1v = *(const float4*)&be1[j0];

#pragma unroll
    for (int nn = 0; nn < 4; nn++) {
        if (!val[nn]) continue;            // warp-uniform
        float dd = (float)degs[nn];
        float inv = dd > 0.f ? 1.f / dd : 0.f;
        float bm  = dd > 0.f ? 1.f : 0.f;
        float t0 = acc[nn][0] * inv + b1v.x * bm;
        float t1 = acc[nn][1] * inv + b1v.y * bm;
        float t2 = acc[nn][2] * inv + b1v.z * bm;
        float t3 = acc[nn][3] * inv + b1v.w * bm;
        float s = t0 + t1 + t2 + t3;
        float q = t0 * t0 + t1 * t1 + t2 * t2 + t3 * t3;
#pragma unroll
        for (int off = 16; off; off >>= 1) {
            s += __shfl_xor_sync(0xffffffffu, s, off);
            q += __shfl_xor_sync(0xffffffffu, q, off);
        }
        float mu = s * (1.f / HH);
        float var = q * (1.f / HH) - mu * mu;
        float rs = rsqrtf(var + LNEPS);
        float4 h;
        h.x = fmaxf((t0 - mu) * rs * g1v.x + be1v.x, 0.f);
        h.y = fmaxf((t1 - mu) * rs * g1v.y + be1v.y, 0.f);
        h.z = fmaxf((t2 - mu) * rs * g1v.z + be1v.z, 0.f);
        h.w = fmaxf((t3 - mu) * rs * g1v.w + be1v.w, 0.f);
        *(float4*)&aw[nn * HH + j0] = h;   // reuse staging for h1
    }
    __syncwarp();

    // ---- GEMM2: xt2 = h1 @ W2^T + b2 (bias unconditional; rides through aggregation) ----
    int j2 = lane * 2;
    float a2[4][2];
#pragma unroll
    for (int nn = 0; nn < 4; nn++) { a2[nn][0] = 0.f; a2[nn][1] = 0.f; }

#pragma unroll 4
    for (int kt = 0; kt < HH / 4; kt++) {
        float2 u0 = *(const float2*)&w2s[(4 * kt + 0) * DO + j2];
        float2 u1 = *(const float2*)&w2s[(4 * kt + 1) * DO + j2];
        float2 u2 = *(const float2*)&w2s[(4 * kt + 2) * DO + j2];
        float2 u3 = *(const float2*)&w2s[(4 * kt + 3) * DO + j2];
#pragma unroll
        for (int nn = 0; nn < 4; nn++) {
            float4 hv = *(const float4*)&aw[nn * HH + 4 * kt];   // broadcast
            a2[nn][0] = fmaf(hv.x, u0.x, fmaf(hv.y, u1.x, fmaf(hv.z, u2.x, fmaf(hv.w, u3.x, a2[nn][0]))));
            a2[nn][1] = fmaf(hv.x, u0.y, fmaf(hv.y, u1.y, fmaf(hv.z, u2.y, fmaf(hv.w, u3.y, a2[nn][1]))));
        }
    }
    float2 b2v = *(const float2*)&b2[j2];
#pragma unroll
    for (int nn = 0; nn < 4; nn++) {
        if (!val[nn]) continue;
        *(float2*)&g_xt2[(size_t)nd[nn] * DO + j2] =
            make_float2(a2[nn][0] + b2v.x, a2[nn][1] + b2v.y);
    }
}

// ---------------- final: gather(xt2 64-dim)/deg + LN -> out ----------------
__global__ void __launch_bounds__(256) k_gather2_ln(const float* __restrict__ g2,
                                                    const float* __restrict__ be2,
                                                    float* __restrict__ out, int n) {
    int gw = (blockIdx.x * blockDim.x + threadIdx.x) >> 5;
    int lane = threadIdx.x & 31;
    if (gw >= n) return;
    int rp0 = g_rowptr[gw], rp1 = g_rowptr[gw + 1];

    float ax = 0.f, ay = 0.f;
    int j = rp0;
    for (; j + 3 < rp1; j += 4) {
        int s0 = g_csr[j], s1 = g_csr[j + 1], s2 = g_csr[j + 2], s3 = g_csr[j + 3];
        float2 v0 = *(const float2*)&g_xt2[(size_t)s0 * DO + lane * 2];
        float2 v1 = *(const float2*)&g_xt2[(size_t)s1 * DO + lane * 2];
        float2 v2 = *(const float2*)&g_xt2[(size_t)s2 * DO + lane * 2];
        float2 v3 = *(const float2*)&g_xt2[(size_t)s3 * DO + lane * 2];
        ax += v0.x; ay += v0.y;
        ax += v1.x; ay += v1.y;
        ax += v2.x; ay += v2.y;
        ax += v3.x; ay += v3.y;
    }
    for (; j < rp1; j++) {
        int s = g_csr[j];
        float2 v = *(const float2*)&g_xt2[(size_t)s * DO + lane * 2];
        ax += v.x; ay += v.y;
    }

    int d = rp1 - rp0;
    float inv = d > 0 ? 1.f / (float)d : 0.f;
    float v0 = ax * inv, v1 = ay * inv;
    float s = v0 + v1, q = v0 * v0 + v1 * v1;
#pragma unroll
    for (int off = 16; off; off >>= 1) {
        s += __shfl_xor_sync(0xffffffffu, s, off);
        q += __shfl_xor_sync(0xffffffffu, q, off);
    }
    float mu = s * (1.f / DO);
    float var = q * (1.f / DO) - mu * mu;
    float rs = rsqrtf(var + LNEPS);
    int j2 = lane * 2;
    float2 o;
    o.x = (v0 - mu) * rs * g2[j2]     + be2[j2];
    o.y = (v1 - mu) * rs * g2[j2 + 1] + be2[j2 + 1];
    *(float2*)&out[(size_t)gw * DO + j2] = o;
}

// ---------------- launch ----------------
extern "C" void kernel_launch(void* const* d_in, const int* in_sizes, int n_in,
                              void* d_out, int out_size) {
    const float* nf  = (const float*)d_in[0];
    const int*   ei  = (const int*)d_in[1];
    const float* W0  = (const float*)d_in[2];
    const float* b0  = (const float*)d_in[3];
    const float* W1  = (const float*)d_in[4];
    const float* b1  = (const float*)d_in[5];
    const float* W2  = (const float*)d_in[6];
    const float* b2  = (const float*)d_in[7];
    const float* g0  = (const float*)d_in[8];
    const float* be0 = (const float*)d_in[9];
    const float* g1  = (const float*)d_in[10];
    const float* be1 = (const float*)d_in[11];
    const float* g2  = (const float*)d_in[12];
    const float* be2 = (const float*)d_in[13];
    float* out = (float*)d_out;

    int n = in_sizes[0] / FIN;
    int e = in_sizes[1] / 2;

    k_init<<<(n + 255) / 256, 256>>>();
    k_prep<<<(HH * HH + 255) / 256, 256>>>(W0, W1, W2);

    // CSR build
    k_hist<<<(e + 255) / 256, 256>>>(ei, e);
    k_scanA<<<NB, 1024>>>(n);
    k_scanB<<<1, 128>>>();
    k_scanC<<<(n + 255) / 256, 256>>>(n, e);
    k_fill<<<(e + 255) / 256, 256>>>(ei, e);

    // fused layers
    k_fused0g<<<(n + 7) / 8, 256>>>(nf, b0, g0, be0, n);

    const int smem12 = (HH * HH + HH * DO + 8 * 4 * HH) * (int)sizeof(float);  // 114688 B
    cudaFuncSetAttribute(k_fused12g, cudaFuncAttributeMaxDynamicSharedMemorySize, smem12);
    k_fused12g<<<(n + 31) / 32, 256, smem12>>>(b1, g1, be1, b2, n);

    k_gather2_ln<<<(n + 7) / 8, 256>>>(g2, be2, out, n);
}